// round 3
// baseline (speedup 1.0000x reference)
#include <cuda_runtime.h>
#include <cstdio>

#define H 128
#define NLAY 3
#define GR 32            // rows per GEMM tile
#define GEMM_BLOCKS 296
#define GEMM_SMEM ((H*H + GR*H) * (int)sizeof(float))   // 81920 B

static const int NMAXc  = 100000;
static const int EMAXc  = 600000;
static const int BMAXc  = 64;

// ---------------- scratch (device globals; allocation-free rule) -----------
__device__ float d_h0[(size_t)NMAXc * H];
__device__ float d_h1[(size_t)NMAXc * H];
__device__ float d_e0[(size_t)EMAXc * H];
__device__ float d_e1[(size_t)EMAXc * H];
__device__ int   d_cntG[2 * NMAXc];
__device__ int   d_cntL[2 * EMAXc];
__device__ float d_dinvG[2 * NMAXc];
__device__ float d_dinvL[2 * EMAXc];
__device__ float d_red[2 * BMAXc * H + 2 * BMAXc];

// ---------------- helpers --------------------------------------------------
__device__ __forceinline__ void red_add_v4(float* p, float4 v) {
    asm volatile("red.global.add.v4.f32 [%0], {%1,%2,%3,%4};"
                 :: "l"(p), "f"(v.x), "f"(v.y), "f"(v.z), "f"(v.w) : "memory");
}

// ---------------- kernels --------------------------------------------------
__global__ void k_zero_f4(float4* __restrict__ p, long long n4) {
    long long i = (long long)blockIdx.x * blockDim.x + threadIdx.x;
    long long st = (long long)gridDim.x * blockDim.x;
    float4 z = make_float4(0.f, 0.f, 0.f, 0.f);
    for (; i < n4; i += st) p[i] = z;
}

__global__ void k_count(const int* __restrict__ s, const int* __restrict__ t,
                        int* __restrict__ co, int* __restrict__ ci, int m) {
    int i = blockIdx.x * blockDim.x + threadIdx.x;
    int st = gridDim.x * blockDim.x;
    for (; i < m; i += st) {
        atomicAdd(&co[s[i]], 1);
        atomicAdd(&ci[t[i]], 1);
    }
}

__global__ void k_dinv(const int* __restrict__ c, float* __restrict__ dv, int n) {
    int i = blockIdx.x * blockDim.x + threadIdx.x;
    int st = gridDim.x * blockDim.x;
    for (; i < n; i += st) dv[i] = rsqrtf(fmaxf((float)c[i], 1.f));
}

// h0[node] = emb[z[node]]   (one warp per node, float4 lanes)
__global__ void k_init_h(const int* __restrict__ z, const float* __restrict__ emb,
                         float* __restrict__ h, int n) {
    int gid = blockIdx.x * blockDim.x + threadIdx.x;
    int node = gid >> 5, lane = gid & 31;
    if (node >= n) return;
    int zz = __ldg(&z[node]);
    float4 v = *(const float4*)(emb + (size_t)zz * H + lane * 4);
    *(float4*)(h + (size_t)node * H + lane * 4) = v;
}

// e0[i] = d[i] * ep_w + ep_b
__global__ void k_init_e(const float* __restrict__ d, const float* __restrict__ w,
                         const float* __restrict__ b, float* __restrict__ e, int m) {
    int gid = blockIdx.x * blockDim.x + threadIdx.x;
    int i = gid >> 5, lane = gid & 31;
    if (i >= m) return;
    float dv = __ldg(&d[i]);
    float4 wv = *(const float4*)(w + lane * 4);
    float4 bv = *(const float4*)(b + lane * 4);
    float4 o;
    o.x = dv * wv.x + bv.x; o.y = dv * wv.y + bv.y;
    o.z = dv * wv.z + bv.z; o.w = dv * wv.w + bv.w;
    *(float4*)(e + (size_t)i * H + lane * 4) = o;
}

// agg[t[e]] += in[s[e]] * dinv_out[s[e]]   (one warp per edge, vector red)
__global__ void k_scatter(const float* __restrict__ in, const float* __restrict__ dinv,
                          const int* __restrict__ s, const int* __restrict__ t,
                          float* __restrict__ agg, int m) {
    int gid = blockIdx.x * blockDim.x + threadIdx.x;
    int e = gid >> 5, lane = gid & 31;
    if (e >= m) return;
    int u = __ldg(&s[e]);
    int v = __ldg(&t[e]);
    float sc = __ldg(&dinv[u]);
    float4 x = *(const float4*)(in + (size_t)u * H + lane * 4);
    x.x *= sc; x.y *= sc; x.z *= sc; x.w *= sc;
    red_add_v4(agg + (size_t)v * H + lane * 4, x);
}

// in-place: buf = relu( (diag(dinv_in) * buf) @ W + b )
// persistent blocks, W resident in smem, 32-row tiles, thread = 4x4 micro-tile
__global__ __launch_bounds__(256) void k_gemm(float* __restrict__ buf,
                                              const float* __restrict__ dinv,
                                              const float* __restrict__ W,
                                              const float* __restrict__ bias,
                                              int n) {
    extern __shared__ float sh[];
    float* Wsh = sh;           // H*H
    float* Rsh = sh + H * H;   // GR*H
    int tid = threadIdx.x;

    // load W (64KB) cooperatively
    #pragma unroll
    for (int q = 0; q < 16; q++) {
        int lin = tid + q * 256;                       // 4096 float4
        ((float4*)Wsh)[lin] = ((const float4*)W)[lin];
    }

    int tx = tid & 31;        // col group: cols [tx*4, tx*4+4)
    int ty = tid >> 5;        // row group: rows [ty*4, ty*4+4) within tile
    float4 bv = *(const float4*)(bias + tx * 4);

    int ntiles = (n + GR - 1) / GR;
    for (int tile = blockIdx.x; tile < ntiles; tile += gridDim.x) {
        int row0 = tile * GR;
        __syncthreads();   // Rsh reuse barrier (also orders W load on first iter)
        // load + scale 32 rows into Rsh [r][k]
        #pragma unroll
        for (int q = 0; q < 4; q++) {
            int lin = tid + q * 256;                   // 1024 float4
            int r = lin >> 5;
            int k4 = lin & 31;
            int row = row0 + r;
            float4 v = make_float4(0.f, 0.f, 0.f, 0.f);
            if (row < n) {
                v = *(const float4*)(buf + (size_t)row * H + k4 * 4);
                float sc = dinv[row];
                v.x *= sc; v.y *= sc; v.z *= sc; v.w *= sc;
            }
            *(float4*)(Rsh + r * H + k4 * 4) = v;
        }
        __syncthreads();

        float acc[4][4];
        #pragma unroll
        for (int rr = 0; rr < 4; rr++) {
            acc[rr][0] = bv.x; acc[rr][1] = bv.y;
            acc[rr][2] = bv.z; acc[rr][3] = bv.w;
        }
        int rbase = ty * 4;
        #pragma unroll 4
        for (int k = 0; k < H; k += 4) {
            float4 w0 = *(float4*)(Wsh + (k + 0) * H + tx * 4);
            float4 w1 = *(float4*)(Wsh + (k + 1) * H + tx * 4);
            float4 w2 = *(float4*)(Wsh + (k + 2) * H + tx * 4);
            float4 w3 = *(float4*)(Wsh + (k + 3) * H + tx * 4);
            #pragma unroll
            for (int rr = 0; rr < 4; rr++) {
                float4 rv = *(float4*)(Rsh + (rbase + rr) * H + k);
                acc[rr][0] += rv.x * w0.x + rv.y * w1.x + rv.z * w2.x + rv.w * w3.x;
                acc[rr][1] += rv.x * w0.y + rv.y * w1.y + rv.z * w2.y + rv.w * w3.y;
                acc[rr][2] += rv.x * w0.z + rv.y * w1.z + rv.z * w2.z + rv.w * w3.z;
                acc[rr][3] += rv.x * w0.w + rv.y * w1.w + rv.z * w2.w + rv.w * w3.w;
            }
        }
        #pragma unroll
        for (int rr = 0; rr < 4; rr++) {
            int row = row0 + rbase + rr;
            if (row < n) {
                float4 o;
                o.x = fmaxf(acc[rr][0], 0.f);
                o.y = fmaxf(acc[rr][1], 0.f);
                o.z = fmaxf(acc[rr][2], 0.f);
                o.w = fmaxf(acc[rr][3], 0.f);
                *(float4*)(buf + (size_t)row * H + tx * 4) = o;
            }
        }
    }
}

// segment sum + count (one warp per row)
__global__ void k_segsum(const float* __restrict__ h, const int* __restrict__ seg,
                         float* __restrict__ sum, float* __restrict__ cnt, int n) {
    int gid = blockIdx.x * blockDim.x + threadIdx.x;
    int i = gid >> 5, lane = gid & 31;
    if (i >= n) return;
    int g = __ldg(&seg[i]);
    float4 v = *(const float4*)(h + (size_t)i * H + lane * 4);
    red_add_v4(sum + (size_t)g * H + lane * 4, v);
    if (lane == 0) atomicAdd(&cnt[g], 1.f);
}

// per-graph readout MLP: y = silu([hg|he] @ r1w + r1b) @ r2w + r2b
__global__ void k_mlp(const float* __restrict__ gsum, const float* __restrict__ esum,
                      const float* __restrict__ gcnt, const float* __restrict__ ecnt,
                      const float* __restrict__ r1w, const float* __restrict__ r1b,
                      const float* __restrict__ r2w, const float* __restrict__ r2b,
                      float* __restrict__ out) {
    __shared__ float x[2 * H];
    __shared__ float red[4];
    int b = blockIdx.x;
    int j = threadIdx.x;                 // 128 threads
    float ig = 1.f / fmaxf(gcnt[b], 1.f);
    float ie = 1.f / fmaxf(ecnt[b], 1.f);
    x[j]     = gsum[b * H + j] * ig;
    x[H + j] = esum[b * H + j] * ie;
    __syncthreads();
    float acc = __ldg(&r1b[j]);
    #pragma unroll 8
    for (int i = 0; i < 2 * H; i++) acc += x[i] * __ldg(&r1w[i * H + j]);
    float sig = 1.f / (1.f + expf(-acc));
    float val = acc * sig * __ldg(&r2w[j]);
    #pragma unroll
    for (int o = 16; o > 0; o >>= 1) val += __shfl_xor_sync(0xffffffffu, val, o);
    if ((j & 31) == 0) red[j >> 5] = val;
    __syncthreads();
    if (j == 0) out[b] = red[0] + red[1] + red[2] + red[3] + __ldg(&r2b[0]);
}

// ---------------- host -----------------------------------------------------
static inline int zgrid(long long n4) {
    long long b = (n4 + 255) / 256;
    return (int)(b < 8192 ? b : 8192);
}

extern "C" void kernel_launch(void* const* d_in, const int* in_sizes, int n_in,
                              void* d_out, int out_size) {
    const int*   z    = (const int*)d_in[0];
    const float* dd   = (const float*)d_in[1];
    const int*   src  = (const int*)d_in[2];
    const int*   dst  = (const int*)d_in[3];
    const int*   lsrc = (const int*)d_in[4];
    const int*   ldst = (const int*)d_in[5];
    const int*   ng   = (const int*)d_in[6];
    const int*   eg   = (const int*)d_in[7];
    const float* emb  = (const float*)d_in[8];
    const float* epw  = (const float*)d_in[9];
    const float* epb  = (const float*)d_in[10];
    const float* gW   = (const float*)d_in[11];
    const float* gb   = (const float*)d_in[12];
    const float* lgW  = (const float*)d_in[13];
    const float* lgb  = (const float*)d_in[14];
    const float* r1w  = (const float*)d_in[15];
    const float* r1b  = (const float*)d_in[16];
    const float* r2w  = (const float*)d_in[17];
    const float* r2b  = (const float*)d_in[18];

    int N  = in_sizes[0];
    int E  = in_sizes[2];
    int E2 = in_sizes[4];
    int B  = out_size;
    float* out = (float*)d_out;

    float *h0, *h1, *e0, *e1, *dinvG, *dinvL, *red;
    int *cntG, *cntL;
    cudaGetSymbolAddress((void**)&h0, d_h0);
    cudaGetSymbolAddress((void**)&h1, d_h1);
    cudaGetSymbolAddress((void**)&e0, d_e0);
    cudaGetSymbolAddress((void**)&e1, d_e1);
    cudaGetSymbolAddress((void**)&cntG, d_cntG);
    cudaGetSymbolAddress((void**)&cntL, d_cntL);
    cudaGetSymbolAddress((void**)&dinvG, d_dinvG);
    cudaGetSymbolAddress((void**)&dinvL, d_dinvL);
    cudaGetSymbolAddress((void**)&red, d_red);

    float* gsum = red;
    float* esum = red + (size_t)B * H;
    float* gcnt = red + (size_t)2 * B * H;
    float* ecnt = gcnt + B;

    cudaFuncSetAttribute(k_gemm, cudaFuncAttributeMaxDynamicSharedMemorySize, GEMM_SMEM);

    // ---- degrees + inits ----
    k_zero_f4<<<zgrid((long long)2 * N / 4), 256>>>((float4*)cntG, (long long)2 * N / 4);
    k_zero_f4<<<zgrid((long long)2 * E / 4), 256>>>((float4*)cntL, (long long)2 * E / 4);
    {
        long long nred4 = ((long long)2 * B * H + 2 * B) / 4;
        k_zero_f4<<<zgrid(nred4), 256>>>((float4*)red, nred4);
    }
    k_count<<<2048, 256>>>(src, dst, cntG, cntG + N, E);
    k_count<<<2048, 256>>>(lsrc, ldst, cntL, cntL + E, E2);
    k_dinv<<<2048, 256>>>(cntG, dinvG, 2 * N);
    k_dinv<<<2048, 256>>>(cntL, dinvL, 2 * E);

    k_init_h<<<((long long)N * 32 + 255) / 256, 256>>>(z, emb, h0, N);
    k_init_e<<<((long long)E * 32 + 255) / 256, 256>>>(dd, epw, epb, e0, E);

    // ---- node-graph conv layers ----
    float* hin = h0; float* hout = h1;
    for (int l = 0; l < NLAY; l++) {
        long long nh4 = (long long)N * H / 4;
        k_zero_f4<<<zgrid(nh4), 256>>>((float4*)hout, nh4);
        k_scatter<<<((long long)E * 32 + 255) / 256, 256>>>(hin, dinvG, src, dst, hout, E);
        k_gemm<<<GEMM_BLOCKS, 256, GEMM_SMEM>>>(hout, dinvG + N, gW + (size_t)l * H * H, gb + (size_t)l * H, N);
        float* t = hin; hin = hout; hout = t;
    }

    // ---- line-graph conv layers ----
    float* ein = e0; float* eout = e1;
    for (int l = 0; l < NLAY; l++) {
        long long ne4 = (long long)E * H / 4;
        k_zero_f4<<<zgrid(ne4), 256>>>((float4*)eout, ne4);
        k_scatter<<<((long long)E2 * 32 + 255) / 256, 256>>>(ein, dinvL, lsrc, ldst, eout, E2);
        k_gemm<<<GEMM_BLOCKS, 256, GEMM_SMEM>>>(eout, dinvL + E, lgW + (size_t)l * H * H, lgb + (size_t)l * H, E);
        float* t = ein; ein = eout; eout = t;
    }

    // ---- readout ----
    k_segsum<<<((long long)N * 32 + 255) / 256, 256>>>(hin, ng, gsum, gcnt, N);
    k_segsum<<<((long long)E * 32 + 255) / 256, 256>>>(ein, eg, esum, ecnt, E);
    k_mlp<<<B, 128>>>(gsum, esum, gcnt, ecnt, r1w, r1b, r2w, r2b, out);
}

// round 4
// speedup vs baseline: 1.0984x; 1.0984x over previous
#include <cuda_runtime.h>
#include <mma.h>
#include <cstdio>

using namespace nvcuda;

#define H 128
#define NLAY 3
#define GEMM_ROWS 64
#define LDS_PAD 136                  // 128 + 8, multiple of 4 elems (16B)
#define GEMM_BLOCKS 296
#define GEMM_SMEM ((H * LDS_PAD + GEMM_ROWS * LDS_PAD) * (int)sizeof(float))  // 104448

static const int NMAXc  = 100000;
static const int EMAXc  = 600000;
static const int E2MAXc = 1500000;
static const int BMAXc  = 64;

// ---------------- scratch (device globals; allocation-free rule) -----------
__device__ float d_hx[(size_t)(NMAXc + 64) * H];
__device__ float d_hy[(size_t)(NMAXc + 64) * H];
__device__ float d_ex[(size_t)(EMAXc + 64) * H];
__device__ float d_ey[(size_t)(EMAXc + 64) * H];
__device__ int   d_cntG[2 * NMAXc];      // [0,N) out-deg, [N,2N) in-deg
__device__ int   d_cntL[2 * EMAXc];
__device__ float d_dinvG[2 * NMAXc];
__device__ float d_dinvL[2 * EMAXc];
__device__ int   d_offG[NMAXc];
__device__ int   d_offL[EMAXc];
__device__ int   d_curG[NMAXc];
__device__ int   d_curL[EMAXc];
__device__ int   d_eidxG[EMAXc];
__device__ int   d_eidxL[E2MAXc];
__device__ int   d_bsum[1024];
__device__ float d_red[2 * BMAXc * H + 2 * BMAXc];

// ---------------- helpers --------------------------------------------------
__device__ __forceinline__ void red_add_v4(float* p, float4 v) {
    asm volatile("red.global.add.v4.f32 [%0], {%1,%2,%3,%4};"
                 :: "l"(p), "f"(v.x), "f"(v.y), "f"(v.z), "f"(v.w) : "memory");
}
__device__ __forceinline__ float to_tf32(float x) {
    float r; asm("cvt.rna.tf32.f32 %0, %1;" : "=f"(r) : "f"(x)); return r;
}

// ---------------- small utility kernels ------------------------------------
__global__ void k_zero_f4(float4* __restrict__ p, long long n4) {
    long long i = (long long)blockIdx.x * blockDim.x + threadIdx.x;
    long long st = (long long)gridDim.x * blockDim.x;
    float4 z = make_float4(0.f, 0.f, 0.f, 0.f);
    for (; i < n4; i += st) p[i] = z;
}

__global__ void k_count(const int* __restrict__ s, const int* __restrict__ t,
                        int* __restrict__ co, int* __restrict__ ci, int m) {
    int i = blockIdx.x * blockDim.x + threadIdx.x;
    int st = gridDim.x * blockDim.x;
    for (; i < m; i += st) {
        atomicAdd(&co[s[i]], 1);
        atomicAdd(&ci[t[i]], 1);
    }
}

__global__ void k_dinv(const int* __restrict__ c, float* __restrict__ dv, int n) {
    int i = blockIdx.x * blockDim.x + threadIdx.x;
    int st = gridDim.x * blockDim.x;
    for (; i < n; i += st) dv[i] = rsqrtf(fmaxf((float)c[i], 1.f));
}

__global__ void k_copy_i(const int* __restrict__ a, int* __restrict__ b, int n) {
    int i = blockIdx.x * blockDim.x + threadIdx.x;
    int st = gridDim.x * blockDim.x;
    for (; i < n; i += st) b[i] = a[i];
}

__global__ void k_segcnt(const int* __restrict__ seg, float* __restrict__ cnt, int n) {
    int i = blockIdx.x * blockDim.x + threadIdx.x;
    int st = gridDim.x * blockDim.x;
    for (; i < n; i += st) atomicAdd(&cnt[seg[i]], 1.f);
}

// ---------------- scan (exclusive, 3 kernels) ------------------------------
#define SCAN_ELEMS 4096
__global__ void k_scan1(const int* __restrict__ in, int* __restrict__ out,
                        int* __restrict__ bsum, int n) {
    __shared__ int sh[32];
    int t = threadIdx.x;
    int base = blockIdx.x * SCAN_ELEMS + t * 4;
    int4 v = make_int4(0, 0, 0, 0);
    if (base + 3 < n) v = *(const int4*)(in + base);
    else {
        if (base     < n) v.x = in[base];
        if (base + 1 < n) v.y = in[base + 1];
        if (base + 2 < n) v.z = in[base + 2];
        if (base + 3 < n) v.w = in[base + 3];
    }
    int s = v.x + v.y + v.z + v.w;
    int lane = t & 31, wid = t >> 5;
    int p = s;
    #pragma unroll
    for (int o = 1; o < 32; o <<= 1) {
        int q = __shfl_up_sync(0xffffffffu, p, o);
        if (lane >= o) p += q;
    }
    if (lane == 31) sh[wid] = p;
    __syncthreads();
    if (wid == 0) {
        int q = sh[lane];
        #pragma unroll
        for (int o = 1; o < 32; o <<= 1) {
            int r = __shfl_up_sync(0xffffffffu, q, o);
            if (lane >= o) q += r;
        }
        sh[lane] = q;
    }
    __syncthreads();
    int excl = p - s + (wid ? sh[wid - 1] : 0);
    int4 o4;
    o4.x = excl; o4.y = excl + v.x; o4.z = o4.y + v.y; o4.w = o4.z + v.z;
    if (base + 3 < n) *(int4*)(out + base) = o4;
    else {
        if (base     < n) out[base]     = o4.x;
        if (base + 1 < n) out[base + 1] = o4.y;
        if (base + 2 < n) out[base + 2] = o4.z;
        if (base + 3 < n) out[base + 3] = o4.w;
    }
    if (t == 1023) bsum[blockIdx.x] = excl + s;
}

__global__ void k_scan2(int* __restrict__ bsum, int nb) {
    __shared__ int sh[32];
    int t = threadIdx.x;
    int v = (t < nb) ? bsum[t] : 0;
    int lane = t & 31, wid = t >> 5;
    int p = v;
    #pragma unroll
    for (int o = 1; o < 32; o <<= 1) {
        int q = __shfl_up_sync(0xffffffffu, p, o);
        if (lane >= o) p += q;
    }
    if (lane == 31) sh[wid] = p;
    __syncthreads();
    if (wid == 0) {
        int q = sh[lane];
        #pragma unroll
        for (int o = 1; o < 32; o <<= 1) {
            int r = __shfl_up_sync(0xffffffffu, q, o);
            if (lane >= o) q += r;
        }
        sh[lane] = q;
    }
    __syncthreads();
    int excl = p - v + (wid ? sh[wid - 1] : 0);
    if (t < nb) bsum[t] = excl;
}

__global__ void k_scan3(int* __restrict__ out, const int* __restrict__ bsum, int n) {
    int add = bsum[blockIdx.x];
    int base = blockIdx.x * SCAN_ELEMS + threadIdx.x * 4;
    #pragma unroll
    for (int j = 0; j < 4; j++)
        if (base + j < n) out[base + j] += add;
}

__global__ void k_fill(const int* __restrict__ s, const int* __restrict__ t,
                       int* __restrict__ cur, int* __restrict__ eidx, int m) {
    int i = blockIdx.x * blockDim.x + threadIdx.x;
    int st = gridDim.x * blockDim.x;
    for (; i < m; i += st) {
        int v = t[i];
        int pos = atomicAdd(&cur[v], 1);
        eidx[pos] = s[i];
    }
}

// ---------------- feature init ---------------------------------------------
__global__ void k_init_h(const int* __restrict__ z, const float* __restrict__ emb,
                         float* __restrict__ h, int n) {
    int gid = blockIdx.x * blockDim.x + threadIdx.x;
    int node = gid >> 5, lane = gid & 31;
    if (node >= n) return;
    int zz = __ldg(&z[node]);
    float4 v = *(const float4*)(emb + (size_t)zz * H + lane * 4);
    *(float4*)(h + (size_t)node * H + lane * 4) = v;
}

__global__ void k_init_e(const float* __restrict__ d, const float* __restrict__ w,
                         const float* __restrict__ b, float* __restrict__ e, int m) {
    int gid = blockIdx.x * blockDim.x + threadIdx.x;
    int i = gid >> 5, lane = gid & 31;
    if (i >= m) return;
    float dv = __ldg(&d[i]);
    float4 wv = *(const float4*)(w + lane * 4);
    float4 bv = *(const float4*)(b + lane * 4);
    float4 o;
    o.x = dv * wv.x + bv.x; o.y = dv * wv.y + bv.y;
    o.z = dv * wv.z + bv.z; o.w = dv * wv.w + bv.w;
    *(float4*)(e + (size_t)i * H + lane * 4) = o;
}

// ---------------- TF32 GEMM: y = (diag(dout) x) @ W ------------------------
__global__ __launch_bounds__(256) void k_gemm(const float* __restrict__ x,
                                              const float* __restrict__ dinv,
                                              const float* __restrict__ W,
                                              float* __restrict__ y, int n) {
    extern __shared__ float sh[];
    float* Ws = sh;                  // H x LDS_PAD
    float* As = sh + H * LDS_PAD;    // GEMM_ROWS x LDS_PAD
    int tid = threadIdx.x;

    // stage W once (tf32-rounded)
    #pragma unroll
    for (int q = 0; q < 16; q++) {
        int i = tid + q * 256;           // 4096 float4
        int r = i >> 5; int c4 = (i & 31) * 4;
        float4 v = *(const float4*)(W + r * H + c4);
        v.x = to_tf32(v.x); v.y = to_tf32(v.y);
        v.z = to_tf32(v.z); v.w = to_tf32(v.w);
        *(float4*)(Ws + r * LDS_PAD + c4) = v;
    }

    int warp = tid >> 5;
    int rt = warp & 3;               // row tile within 64 rows
    int cbase = (warp >> 2) * 64;    // col half

    int ntiles = (n + GEMM_ROWS - 1) / GEMM_ROWS;
    for (int tile = blockIdx.x; tile < ntiles; tile += gridDim.x) {
        int row0 = tile * GEMM_ROWS;
        __syncthreads();
        // stage 64 rows of x, scaled + tf32-rounded (buffers padded: no guards)
        #pragma unroll
        for (int q = 0; q < 8; q++) {
            int i = tid + q * 256;       // 2048 float4
            int r = i >> 5; int c4 = (i & 31) * 4;
            int row = row0 + r;
            float sc = dinv[row];
            float4 v = *(const float4*)(x + (size_t)row * H + c4);
            v.x = to_tf32(v.x * sc); v.y = to_tf32(v.y * sc);
            v.z = to_tf32(v.z * sc); v.w = to_tf32(v.w * sc);
            *(float4*)(As + r * LDS_PAD + c4) = v;
        }
        __syncthreads();

        wmma::fragment<wmma::accumulator, 16, 16, 8, float> fc[4];
        #pragma unroll
        for (int t = 0; t < 4; t++) wmma::fill_fragment(fc[t], 0.f);

        #pragma unroll
        for (int k = 0; k < H; k += 8) {
            wmma::fragment<wmma::matrix_a, 16, 16, 8, wmma::precision::tf32, wmma::row_major> fa;
            wmma::load_matrix_sync(fa, As + rt * 16 * LDS_PAD + k, LDS_PAD);
            #pragma unroll
            for (int t = 0; t < 4; t++) {
                wmma::fragment<wmma::matrix_b, 16, 16, 8, wmma::precision::tf32, wmma::row_major> fb;
                wmma::load_matrix_sync(fb, Ws + k * LDS_PAD + cbase + t * 16, LDS_PAD);
                wmma::mma_sync(fc[t], fa, fb, fc[t]);
            }
        }
        #pragma unroll
        for (int t = 0; t < 4; t++)
            wmma::store_matrix_sync(y + (size_t)(row0 + rt * 16) * H + cbase + t * 16,
                                    fc[t], H, wmma::mem_row_major);
    }
}

// ---------------- CSR gather aggregation + fused epilogue ------------------
// out[v] = relu( din[v] * sum_{e in CSR(v)} y[eidx[e]] + b ); LAST: red into gsum
template<int LAST>
__global__ void k_agg(const float* __restrict__ y, const int* __restrict__ eidx,
                      const int* __restrict__ off, const int* __restrict__ cnt,
                      const float* __restrict__ din, const float* __restrict__ bias,
                      float* __restrict__ out, const int* __restrict__ seg,
                      float* __restrict__ gsum, int n) {
    int gid = blockIdx.x * blockDim.x + threadIdx.x;
    int v = gid >> 5, lane = gid & 31;
    if (v >= n) return;
    int start = __ldg(&off[v]);
    int deg = __ldg(&cnt[v]);
    float4 acc = make_float4(0.f, 0.f, 0.f, 0.f);
    int j = 0;
    for (; j + 2 <= deg; j += 2) {
        int u0 = __ldg(&eidx[start + j]);
        int u1 = __ldg(&eidx[start + j + 1]);
        float4 a = *(const float4*)(y + (size_t)u0 * H + lane * 4);
        float4 b = *(const float4*)(y + (size_t)u1 * H + lane * 4);
        acc.x += a.x + b.x; acc.y += a.y + b.y;
        acc.z += a.z + b.z; acc.w += a.w + b.w;
    }
    if (j < deg) {
        int u = __ldg(&eidx[start + j]);
        float4 a = *(const float4*)(y + (size_t)u * H + lane * 4);
        acc.x += a.x; acc.y += a.y; acc.z += a.z; acc.w += a.w;
    }
    float s = __ldg(&din[v]);
    float4 bb = *(const float4*)(bias + lane * 4);
    float4 o;
    o.x = fmaxf(fmaf(s, acc.x, bb.x), 0.f);
    o.y = fmaxf(fmaf(s, acc.y, bb.y), 0.f);
    o.z = fmaxf(fmaf(s, acc.z, bb.z), 0.f);
    o.w = fmaxf(fmaf(s, acc.w, bb.w), 0.f);
    if (LAST) {
        int g = __ldg(&seg[v]);
        red_add_v4(gsum + (size_t)g * H + lane * 4, o);
    } else {
        *(float4*)(out + (size_t)v * H + lane * 4) = o;
    }
}

// ---------------- readout MLP ----------------------------------------------
__global__ void k_mlp(const float* __restrict__ gsum, const float* __restrict__ esum,
                      const float* __restrict__ gcnt, const float* __restrict__ ecnt,
                      const float* __restrict__ r1w, const float* __restrict__ r1b,
                      const float* __restrict__ r2w, const float* __restrict__ r2b,
                      float* __restrict__ out) {
    __shared__ float x[2 * H];
    __shared__ float red[4];
    int b = blockIdx.x;
    int j = threadIdx.x;
    float ig = 1.f / fmaxf(gcnt[b], 1.f);
    float ie = 1.f / fmaxf(ecnt[b], 1.f);
    x[j]     = gsum[b * H + j] * ig;
    x[H + j] = esum[b * H + j] * ie;
    __syncthreads();
    float acc = __ldg(&r1b[j]);
    #pragma unroll 8
    for (int i = 0; i < 2 * H; i++) acc += x[i] * __ldg(&r1w[i * H + j]);
    float sig = 1.f / (1.f + expf(-acc));
    float val = acc * sig * __ldg(&r2w[j]);
    #pragma unroll
    for (int o = 16; o > 0; o >>= 1) val += __shfl_xor_sync(0xffffffffu, val, o);
    if ((j & 31) == 0) red[j >> 5] = val;
    __syncthreads();
    if (j == 0) out[b] = red[0] + red[1] + red[2] + red[3] + __ldg(&r2b[0]);
}

// ---------------- host -----------------------------------------------------
static inline int zgrid(long long n4) {
    long long b = (n4 + 255) / 256;
    return (int)(b < 8192 ? b : 8192);
}

extern "C" void kernel_launch(void* const* d_in, const int* in_sizes, int n_in,
                              void* d_out, int out_size) {
    const int*   z    = (const int*)d_in[0];
    const float* dd   = (const float*)d_in[1];
    const int*   src  = (const int*)d_in[2];
    const int*   dst  = (const int*)d_in[3];
    const int*   lsrc = (const int*)d_in[4];
    const int*   ldst = (const int*)d_in[5];
    const int*   ng   = (const int*)d_in[6];
    const int*   eg   = (const int*)d_in[7];
    const float* emb  = (const float*)d_in[8];
    const float* epw  = (const float*)d_in[9];
    const float* epb  = (const float*)d_in[10];
    const float* gW   = (const float*)d_in[11];
    const float* gb   = (const float*)d_in[12];
    const float* lgW  = (const float*)d_in[13];
    const float* lgb  = (const float*)d_in[14];
    const float* r1w  = (const float*)d_in[15];
    const float* r1b  = (const float*)d_in[16];
    const float* r2w  = (const float*)d_in[17];
    const float* r2b  = (const float*)d_in[18];

    int N  = in_sizes[0];
    int E  = in_sizes[2];
    int E2 = in_sizes[4];
    int B  = out_size;
    float* out = (float*)d_out;

    float *hx, *hy, *ex, *ey, *dinvG, *dinvL, *red;
    int *cntG, *cntL, *offG, *offL, *curG, *curL, *eidxG, *eidxL, *bsum;
    cudaGetSymbolAddress((void**)&hx, d_hx);
    cudaGetSymbolAddress((void**)&hy, d_hy);
    cudaGetSymbolAddress((void**)&ex, d_ex);
    cudaGetSymbolAddress((void**)&ey, d_ey);
    cudaGetSymbolAddress((void**)&cntG, d_cntG);
    cudaGetSymbolAddress((void**)&cntL, d_cntL);
    cudaGetSymbolAddress((void**)&dinvG, d_dinvG);
    cudaGetSymbolAddress((void**)&dinvL, d_dinvL);
    cudaGetSymbolAddress((void**)&offG, d_offG);
    cudaGetSymbolAddress((void**)&offL, d_offL);
    cudaGetSymbolAddress((void**)&curG, d_curG);
    cudaGetSymbolAddress((void**)&curL, d_curL);
    cudaGetSymbolAddress((void**)&eidxG, d_eidxG);
    cudaGetSymbolAddress((void**)&eidxL, d_eidxL);
    cudaGetSymbolAddress((void**)&bsum, d_bsum);
    cudaGetSymbolAddress((void**)&red, d_red);

    float* gsum = red;
    float* esum = red + (size_t)B * H;
    float* gcnt = red + (size_t)2 * B * H;
    float* ecnt = gcnt + B;

    cudaFuncSetAttribute(k_gemm, cudaFuncAttributeMaxDynamicSharedMemorySize, GEMM_SMEM);

    // ---- zero small state ----
    k_zero_f4<<<zgrid((long long)2 * N / 4), 256>>>((float4*)cntG, (long long)2 * N / 4);
    k_zero_f4<<<zgrid((long long)2 * E / 4), 256>>>((float4*)cntL, (long long)2 * E / 4);
    {
        long long nred4 = ((long long)2 * B * H + 2 * B) / 4;
        k_zero_f4<<<zgrid(nred4), 256>>>((float4*)red, nred4);
    }

    // ---- degrees + dinv ----
    k_count<<<2048, 256>>>(src, dst, cntG, cntG + N, E);
    k_count<<<2048, 256>>>(lsrc, ldst, cntL, cntL + E, E2);
    k_dinv<<<2048, 256>>>(cntG, dinvG, 2 * N);
    k_dinv<<<2048, 256>>>(cntL, dinvL, 2 * E);

    // ---- CSR by destination (node graph) ----
    int nbG = (N + SCAN_ELEMS - 1) / SCAN_ELEMS;
    k_scan1<<<nbG, 1024>>>(cntG + N, offG, bsum, N);
    k_scan2<<<1, 1024>>>(bsum, nbG);
    k_scan3<<<nbG, 1024>>>(offG, bsum, N);
    k_copy_i<<<512, 256>>>(offG, curG, N);
    k_fill<<<2048, 256>>>(src, dst, curG, eidxG, E);

    // ---- CSR by destination (line graph) ----
    int nbL = (E + SCAN_ELEMS - 1) / SCAN_ELEMS;
    k_scan1<<<nbL, 1024>>>(cntL + E, offL, bsum, E);
    k_scan2<<<1, 1024>>>(bsum, nbL);
    k_scan3<<<nbL, 1024>>>(offL, bsum, E);
    k_copy_i<<<2048, 256>>>(offL, curL, E);
    k_fill<<<2048, 256>>>(lsrc, ldst, curL, eidxL, E2);

    // ---- per-graph element counts ----
    k_segcnt<<<512, 256>>>(ng, gcnt, N);
    k_segcnt<<<2048, 256>>>(eg, ecnt, E);

    // ---- feature init ----
    k_init_h<<<((long long)N * 32 + 255) / 256, 256>>>(z, emb, hx, N);
    k_init_e<<<((long long)E * 32 + 255) / 256, 256>>>(dd, epw, epb, ex, E);

    // ---- node-graph conv layers (GEMM-first, fused CSR aggregation) ----
    for (int l = 0; l < NLAY; l++) {
        k_gemm<<<GEMM_BLOCKS, 256, GEMM_SMEM>>>(hx, dinvG, gW + (size_t)l * H * H, hy, N);
        if (l < NLAY - 1)
            k_agg<0><<<((long long)N * 32 + 255) / 256, 256>>>(
                hy, eidxG, offG, cntG + N, dinvG + N, gb + (size_t)l * H,
                hx, ng, gsum, N);
        else
            k_agg<1><<<((long long)N * 32 + 255) / 256, 256>>>(
                hy, eidxG, offG, cntG + N, dinvG + N, gb + (size_t)l * H,
                hx, ng, gsum, N);
    }

    // ---- line-graph conv layers ----
    for (int l = 0; l < NLAY; l++) {
        k_gemm<<<GEMM_BLOCKS, 256, GEMM_SMEM>>>(ex, dinvL, lgW + (size_t)l * H * H, ey, E);
        if (l < NLAY - 1)
            k_agg<0><<<((long long)E * 32 + 255) / 256, 256>>>(
                ey, eidxL, offL, cntL + E, dinvL + E, lgb + (size_t)l * H,
                ex, eg, esum, E);
        else
            k_agg<1><<<((long long)E * 32 + 255) / 256, 256>>>(
                ey, eidxL, offL, cntL + E, dinvL + E, lgb + (size_t)l * H,
                ex, eg, esum, E);
    }

    // ---- readout ----
    k_mlp<<<B, 128>>>(gsum, esum, gcnt, ecnt, r1w, r1b, r2w, r2b, out);
}